// round 2
// baseline (speedup 1.0000x reference)
#include <cuda_runtime.h>

// Problem constants
#define T_STEPS 512
#define BATCH   128
#define HDIM    1024
#define G4      4096   // 4*H
#define NBLK    128    // persistent-kernel grid size (<= 148 SMs -> co-resident)

// ---------------- static device scratch (no runtime allocation) -------------
__device__ float g_gx[(size_t)T_STEPS * BATCH * G4];   // 1 GiB: input-projected gates
__device__ float g_hA[BATCH * HDIM];
__device__ float g_hB[BATCH * HDIM];
__device__ float g_c [BATCH * HDIM];
__device__ int   g_len[BATCH];

// grid-barrier state (generation counter survives across launches/replays)
__device__ unsigned          g_count = 0;
__device__ volatile unsigned g_gen   = 0;

// ---------------- helpers ----------------------------------------------------
__device__ __forceinline__ float sigf(float x) { return 1.0f / (1.0f + expf(-x)); }

// Sense-reversal grid barrier. Valid because all NBLK CTAs are co-resident
// (NBLK=128 <= 148 SMs, 1 CTA/SM at our resource usage).
__device__ __forceinline__ void grid_sync() {
    __syncthreads();
    if (threadIdx.x == 0) {
        unsigned my = g_gen;                 // volatile read
        __threadfence();                     // my writes visible before arrive
        unsigned old = atomicAdd(&g_count, 1u);
        if (old == NBLK - 1) {
            g_count = 0;                     // reset BEFORE release
            __threadfence();
            g_gen = my + 1;                  // release
        } else {
            while (g_gen == my) { }          // spin on one L2 line
        }
    }
    __syncthreads();
}

// Decode lengths: harness may hand us int64 or int32 depending on jax x64 config.
// For int64 (little endian) with values < 2^31, every odd 32-bit word is 0.
__global__ void decode_lengths(const int* __restrict__ lraw) {
    __shared__ int odd_nonzero;
    if (threadIdx.x == 0) odd_nonzero = 0;
    __syncthreads();
    if (threadIdx.x < 64) {            // touch only first 128 int32 words (safe for both)
        if (lraw[2 * threadIdx.x + 1] != 0) atomicOr(&odd_nonzero, 1);
    }
    __syncthreads();
    int len = odd_nonzero ? lraw[threadIdx.x]        // int32 layout
                          : lraw[2 * threadIdx.x];   // int64 layout (low word)
    g_len[threadIdx.x] = len;
}

// ---------------- big GEMM: gx = A[M,1024] @ W[1024,4096] + bias -------------
// 128x128 CTA tile, BK=8, 256 threads, 8x8 per thread.
__global__ void __launch_bounds__(256, 2) gemm_gx(
    const float* __restrict__ A, const float* __restrict__ W,
    const float* __restrict__ bias, float* __restrict__ C) {
    const int K = 1024, N = 4096;
    __shared__ float As[8][128];
    __shared__ float Bs[8][128];

    int m0 = blockIdx.y * 128;
    int n0 = blockIdx.x * 128;
    int tid = threadIdx.x;
    int ty = tid >> 4, tx = tid & 15;
    int rm = ty * 8, cn = tx * 8;

    int a_row = tid >> 1, a_k = (tid & 1) * 4;       // 128x8 A tile: 256 float4
    int b_row = tid >> 5, b_col = (tid & 31) * 4;    // 8x128 B tile: 256 float4

    const float* Ag = A + (size_t)(m0 + a_row) * K + a_k;
    const float* Wg = W + (size_t)b_row * N + n0 + b_col;

    float acc[8][8];
#pragma unroll
    for (int i = 0; i < 8; i++)
#pragma unroll
        for (int j = 0; j < 8; j++) acc[i][j] = 0.0f;

    for (int k0 = 0; k0 < K; k0 += 8) {
        float4 av = *(const float4*)(Ag + k0);
        As[a_k + 0][a_row] = av.x;
        As[a_k + 1][a_row] = av.y;
        As[a_k + 2][a_row] = av.z;
        As[a_k + 3][a_row] = av.w;
        *(float4*)&Bs[b_row][b_col] = *(const float4*)(Wg + (size_t)k0 * N);
        __syncthreads();
#pragma unroll
        for (int kk = 0; kk < 8; kk++) {
            float a[8], b[8];
            *(float4*)(a)     = *(const float4*)&As[kk][rm];
            *(float4*)(a + 4) = *(const float4*)&As[kk][rm + 4];
            *(float4*)(b)     = *(const float4*)&Bs[kk][cn];
            *(float4*)(b + 4) = *(const float4*)&Bs[kk][cn + 4];
#pragma unroll
            for (int i = 0; i < 8; i++)
#pragma unroll
                for (int j = 0; j < 8; j++)
                    acc[i][j] += a[i] * b[j];
        }
        __syncthreads();
    }

    float bj[8];
#pragma unroll
    for (int j = 0; j < 8; j++) bj[j] = bias[n0 + cn + j];
#pragma unroll
    for (int i = 0; i < 8; i++) {
        float4 v0, v1;
        v0.x = acc[i][0] + bj[0]; v0.y = acc[i][1] + bj[1];
        v0.z = acc[i][2] + bj[2]; v0.w = acc[i][3] + bj[3];
        v1.x = acc[i][4] + bj[4]; v1.y = acc[i][5] + bj[5];
        v1.z = acc[i][6] + bj[6]; v1.w = acc[i][7] + bj[7];
        float* cp = C + (size_t)(m0 + rm + i) * N + n0 + cn;
        *(float4*)cp       = v0;
        *(float4*)(cp + 4) = v1;
    }
}

// ---------------- persistent recurrence: all 512 steps in ONE launch --------
// 128 CTAs. CTA bid owns batch rows [m0,m0+64) x h-cols [c0,c0+16)
// (= 64 gate-cols across the 4 gates). Per step: gates = gx[t] + h @ Whh for
// its tile, then the LSTM cell update on its 64x16 cells, then a grid barrier.
// h ping-pongs between g_hA / g_hB; c/out slices are CTA-private.
__global__ void __launch_bounds__(256) lstm_layer_persist(
    const float* __restrict__ gx,    // [T,BATCH,4096] (bias included)
    const float* __restrict__ Wh,    // [1024, 4096]
    float* __restrict__ out,         // [T,BATCH,HDIM]
    float* __restrict__ hN,          // [BATCH,HDIM] final h for this layer
    float* __restrict__ cN) {        // [BATCH,HDIM] final c for this layer
    __shared__ float As[16][64];
    __shared__ float Bs[16][64];
    __shared__ float Gs[64][65];

    const int bid = blockIdx.x;
    const int c0 = (bid & 63) * 16;  // h-column base
    const int m0 = (bid >> 6) * 64;  // batch-row base
    const int tid = threadIdx.x;
    const int ty = tid >> 4, tx = tid & 15;
    const int rm = ty * 4, cn = tx * 4;

    // A tile loader: 64 rows x 16 k, thread -> 1 float4
    const int ar = tid >> 2, ak = (tid & 3) * 4;
    // B tile loader: 16 k-rows x 64 gate-cols, thread -> 1 float4
    const int bk = tid >> 4, bq = tid & 15;
    const float* Wg = Wh + (size_t)bk * G4 + (bq >> 2) * HDIM + c0 + (bq & 3) * 4;

    // zero this CTA's h/c slice, then wait for everyone
    for (int e = tid; e < 1024; e += 256) {
        int row = e >> 4, hc = e & 15;
        size_t gi = (size_t)(m0 + row) * HDIM + c0 + hc;
        g_hA[gi] = 0.0f;
        g_c[gi]  = 0.0f;
    }
    grid_sync();

    for (int t = 0; t < T_STEPS; t++) {
        const float* h_in  = (t & 1) ? g_hB : g_hA;
        float*       h_out = (t & 1) ? g_hA : g_hB;
        const float* gxt = gx + (size_t)t * BATCH * G4;
        float*       out_t = out + (size_t)t * BATCH * HDIM;

        const float* Ag = h_in + (size_t)(m0 + ar) * HDIM + ak;

        float acc[4][4];
#pragma unroll
        for (int i = 0; i < 4; i++)
#pragma unroll
            for (int j = 0; j < 4; j++) acc[i][j] = 0.0f;

        for (int k0 = 0; k0 < HDIM; k0 += 16) {
            float4 av = *(const float4*)(Ag + k0);
            As[ak + 0][ar] = av.x;
            As[ak + 1][ar] = av.y;
            As[ak + 2][ar] = av.z;
            As[ak + 3][ar] = av.w;
            *(float4*)&Bs[bk][bq * 4] = *(const float4*)(Wg + (size_t)k0 * G4);
            __syncthreads();
#pragma unroll
            for (int kk = 0; kk < 16; kk++) {
                float a4[4], b4[4];
                *(float4*)a4 = *(const float4*)&As[kk][rm];
                *(float4*)b4 = *(const float4*)&Bs[kk][cn];
#pragma unroll
                for (int i = 0; i < 4; i++)
#pragma unroll
                    for (int j = 0; j < 4; j++)
                        acc[i][j] += a4[i] * b4[j];
            }
            __syncthreads();
        }

        // gates tile -> smem (add precomputed input projection)
#pragma unroll
        for (int i = 0; i < 4; i++) {
#pragma unroll
            for (int j = 0; j < 4; j++) {
                int cc = cn + j;
                int gcol = (cc >> 4) * HDIM + c0 + (cc & 15);
                Gs[rm + i][cc] = acc[i][j] + gxt[(size_t)(m0 + rm + i) * G4 + gcol];
            }
        }
        __syncthreads();

        // cell update: 64 rows x 16 h-cols = 1024 cells, 4 per thread
        for (int e = tid; e < 1024; e += 256) {
            int row = e >> 4, hc = e & 15;
            float iv = Gs[row][hc];
            float fv = Gs[row][16 + hc];
            float ov = Gs[row][32 + hc];
            float gv = Gs[row][48 + hc];
            size_t gi = (size_t)(m0 + row) * HDIM + c0 + hc;
            float cp = g_c[gi];
            float hp = h_in[gi];
            float c1 = sigf(fv + 1.0f) * cp + sigf(iv) * tanhf(gv);
            float h1 = sigf(ov) * tanhf(c1);
            bool msk = t < g_len[m0 + row];
            h_out[gi] = msk ? h1 : hp;
            g_c[gi]   = msk ? c1 : cp;
            out_t[gi] = msk ? h1 : 0.0f;
        }
        grid_sync();   // h_out fully written before anyone reads it at t+1
    }

    // after t=511 (odd), the latest h lives in g_hA; each CTA copies its slice
    for (int e = tid; e < 1024; e += 256) {
        int row = e >> 4, hc = e & 15;
        size_t gi = (size_t)(m0 + row) * HDIM + c0 + hc;
        hN[gi] = g_hA[gi];
        cN[gi] = g_c[gi];
    }
}

// ---------------- launch -----------------------------------------------------
extern "C" void kernel_launch(void* const* d_in, const int* in_sizes, int n_in,
                              void* d_out, int out_size) {
    (void)in_sizes; (void)n_in; (void)out_size;

    const float* x    = (const float*)d_in[0];   // [512,128,1024]
    const int*   lraw = (const int*)d_in[1];     // [128] int32 or int64
    const float* Wih  = (const float*)d_in[2];   // [2,1024,4096]
    const float* Whh  = (const float*)d_in[3];   // [2,1024,4096]
    const float* bias = (const float*)d_in[4];   // [2,4096]

    float* out = (float*)d_out;                         // [512,128,1024]
    float* hN  = out + (size_t)T_STEPS * BATCH * HDIM;  // [2,128,1024]
    float* cN  = hN + 2 * BATCH * HDIM;                 // [2,128,1024]

    float* gx;
    cudaGetSymbolAddress((void**)&gx, g_gx);

    decode_lengths<<<1, 128>>>(lraw);

    for (int l = 0; l < 2; l++) {
        // layer 0 reads x; layer 1 reads layer-0 outputs staged in d_out's
        // "out" region (fully consumed by gemm_gx before the persist kernel
        // starts overwriting it — stream order guarantees this)
        const float* in = (l == 0) ? x : out;
        const float* Wi = Wih + (size_t)l * HDIM * G4;
        const float* Wh = Whh + (size_t)l * HDIM * G4;
        const float* bi = bias + (size_t)l * G4;

        gemm_gx<<<dim3(32, 512), 256>>>(in, Wi, bi, gx);
        lstm_layer_persist<<<NBLK, 256>>>(
            gx, Wh, out,
            hN + (size_t)l * BATCH * HDIM,
            cN + (size_t)l * BATCH * HDIM);
    }
}

// round 4
// speedup vs baseline: 2.5225x; 2.5225x over previous
#include <cuda_runtime.h>
#include <cuda_bf16.h>
#include <cstdint>

// ---------------- problem constants ----------------
#define T_STEPS 512
#define BATCH   128
#define HDIM    1024
#define G4      4096
#define NBLK    128      // persistent CTAs (<=148 SMs, co-resident)
#define NTHR    256      // threads per persistent CTA (8 warps)

// ---------------- warp MMA helpers (mma.sync, sm_80+ PTX -> HMMA) -----------
__device__ __forceinline__ uint32_t smem_u32(const void* p) {
    uint32_t a;
    asm("{ .reg .u64 t; cvta.to.shared.u64 t, %1; cvt.u32.u64 %0, t; }"
        : "=r"(a) : "l"(p));
    return a;
}

#define LDSM_X4(r0, r1, r2, r3, addr)                                          \
    asm volatile("ldmatrix.sync.aligned.m8n8.x4.shared.b16 {%0,%1,%2,%3}, [%4];" \
                 : "=r"(r0), "=r"(r1), "=r"(r2), "=r"(r3) : "r"(addr))

#define LDSM_X4T(r0, r1, r2, r3, addr)                                         \
    asm volatile("ldmatrix.sync.aligned.m8n8.x4.trans.shared.b16 {%0,%1,%2,%3}, [%4];" \
                 : "=r"(r0), "=r"(r1), "=r"(r2), "=r"(r3) : "r"(addr))

// D += A(16x16 bf16, row) * B(16x8 bf16, col), fp32 accum
#define MMA16816(d, a, b0, b1)                                                 \
    asm volatile("mma.sync.aligned.m16n8k16.row.col.f32.bf16.bf16.f32 "        \
                 "{%0,%1,%2,%3}, {%4,%5,%6,%7}, {%8,%9}, {%0,%1,%2,%3};"       \
                 : "+f"((d)[0]), "+f"((d)[1]), "+f"((d)[2]), "+f"((d)[3])      \
                 : "r"((a)[0]), "r"((a)[1]), "r"((a)[2]), "r"((a)[3]),         \
                   "r"(b0), "r"(b1))

// ---------------- static device scratch ----------------
__device__ float          g_gx[(size_t)T_STEPS * BATCH * G4];   // 1 GiB
__device__ float          g_h  [BATCH * HDIM];
__device__ float          g_c  [BATCH * HDIM];
__device__ __nv_bfloat16  g_h_hi[BATCH * HDIM];
__device__ __nv_bfloat16  g_h_lo[BATCH * HDIM];
__device__ float          g_part[(size_t)4 * BATCH * G4];       // 4 K-split partials
__device__ int            g_len[BATCH];

__device__ unsigned          g_count = 0;
__device__ volatile unsigned g_gen   = 0;

// ---------------- helpers ----------------
__device__ __forceinline__ float sigf(float x) { return 1.0f / (1.0f + expf(-x)); }

__device__ __forceinline__ void grid_sync() {
    __threadfence();
    __syncthreads();
    if (threadIdx.x == 0) {
        unsigned my = g_gen;
        unsigned old = atomicAdd(&g_count, 1u);
        if (old == NBLK - 1) {
            g_count = 0;
            __threadfence();
            g_gen = my + 1;
        } else {
            while (g_gen == my) { }
        }
    }
    __syncthreads();
}

__global__ void decode_lengths(const int* __restrict__ lraw) {
    __shared__ int odd_nonzero;
    if (threadIdx.x == 0) odd_nonzero = 0;
    __syncthreads();
    if (threadIdx.x < 64) {
        if (lraw[2 * threadIdx.x + 1] != 0) atomicOr(&odd_nonzero, 1);
    }
    __syncthreads();
    int len = odd_nonzero ? lraw[threadIdx.x] : lraw[2 * threadIdx.x];
    g_len[threadIdx.x] = len;
}

// ---------------- big GEMM: gx = A[M,1024] @ W[1024,4096] + bias ------------
// bf16x3 split on tensor cores. CTA tile 128x128, BK=32, 8 warps (32x64 each).
__global__ void __launch_bounds__(256) gemm_gx_mma(
    const float* __restrict__ A, const float* __restrict__ W,
    const float* __restrict__ bias, float* __restrict__ C) {
    __shared__ __nv_bfloat16 AsHi[128][40];   // pad 8 -> conflict-free ldmatrix
    __shared__ __nv_bfloat16 AsLo[128][40];
    __shared__ __nv_bfloat16 BsHi[32][136];
    __shared__ __nv_bfloat16 BsLo[32][136];

    const int m0 = blockIdx.y * 128, n0 = blockIdx.x * 128;
    const int tid = threadIdx.x, wid = tid >> 5, lane = tid & 31;
    const int wm = (wid & 3) * 32;   // warp row base (2 m16 tiles)
    const int wn = (wid >> 2) * 64;  // warp col base (8 n8 tiles)

    float acc[2][8][4];
#pragma unroll
    for (int i = 0; i < 2; i++)
#pragma unroll
        for (int j = 0; j < 8; j++)
#pragma unroll
            for (int v = 0; v < 4; v++) acc[i][j][v] = 0.0f;

    // ldmatrix lane address offsets (within tile)
    const uint32_t aOffH = smem_u32(AsHi) + ((wm + (lane & 15)) * 40 + (lane >> 4) * 8) * 2;
    const uint32_t aOffL = smem_u32(AsLo) + ((wm + (lane & 15)) * 40 + (lane >> 4) * 8) * 2;
    const uint32_t bOffH = smem_u32(BsHi) + ((lane & 15) * 136 + wn + (lane >> 4) * 8) * 2;
    const uint32_t bOffL = smem_u32(BsLo) + ((lane & 15) * 136 + wn + (lane >> 4) * 8) * 2;

    for (int k0 = 0; k0 < 1024; k0 += 32) {
        // ---- load + convert A tile (128x32 fp32 -> bf16 hi/lo) ----
#pragma unroll
        for (int i = 0; i < 4; i++) {
            int idx = tid + i * 256;
            int r = idx >> 3, c = (idx & 7) * 4;
            float4 v = *(const float4*)(A + (size_t)(m0 + r) * 1024 + k0 + c);
            __nv_bfloat16 h0 = __float2bfloat16_rn(v.x);
            __nv_bfloat16 h1 = __float2bfloat16_rn(v.y);
            __nv_bfloat16 h2 = __float2bfloat16_rn(v.z);
            __nv_bfloat16 h3 = __float2bfloat16_rn(v.w);
            __nv_bfloat16 l0 = __float2bfloat16_rn(v.x - __bfloat162float(h0));
            __nv_bfloat16 l1 = __float2bfloat16_rn(v.y - __bfloat162float(h1));
            __nv_bfloat16 l2 = __float2bfloat16_rn(v.z - __bfloat162float(h2));
            __nv_bfloat16 l3 = __float2bfloat16_rn(v.w - __bfloat162float(h3));
            *(__nv_bfloat162*)&AsHi[r][c]     = __halves2bfloat162(h0, h1);
            *(__nv_bfloat162*)&AsHi[r][c + 2] = __halves2bfloat162(h2, h3);
            *(__nv_bfloat162*)&AsLo[r][c]     = __halves2bfloat162(l0, l1);
            *(__nv_bfloat162*)&AsLo[r][c + 2] = __halves2bfloat162(l2, l3);
        }
        // ---- load + convert W tile (32x128) ----
#pragma unroll
        for (int i = 0; i < 4; i++) {
            int idx = tid + i * 256;
            int kr = idx >> 5, nc = (idx & 31) * 4;
            float4 v = *(const float4*)(W + (size_t)(k0 + kr) * G4 + n0 + nc);
            __nv_bfloat16 h0 = __float2bfloat16_rn(v.x);
            __nv_bfloat16 h1 = __float2bfloat16_rn(v.y);
            __nv_bfloat16 h2 = __float2bfloat16_rn(v.z);
            __nv_bfloat16 h3 = __float2bfloat16_rn(v.w);
            __nv_bfloat16 l0 = __float2bfloat16_rn(v.x - __bfloat162float(h0));
            __nv_bfloat16 l1 = __float2bfloat16_rn(v.y - __bfloat162float(h1));
            __nv_bfloat16 l2 = __float2bfloat16_rn(v.z - __bfloat162float(h2));
            __nv_bfloat16 l3 = __float2bfloat16_rn(v.w - __bfloat162float(h3));
            *(__nv_bfloat162*)&BsHi[kr][nc]     = __halves2bfloat162(h0, h1);
            *(__nv_bfloat162*)&BsHi[kr][nc + 2] = __halves2bfloat162(h2, h3);
            *(__nv_bfloat162*)&BsLo[kr][nc]     = __halves2bfloat162(l0, l1);
            *(__nv_bfloat162*)&BsLo[kr][nc + 2] = __halves2bfloat162(l2, l3);
        }
        __syncthreads();

#pragma unroll
        for (int ks = 0; ks < 2; ks++) {
            const int kk = ks * 16;
            uint32_t aH[2][4], aL[2][4];
#pragma unroll
            for (int mt = 0; mt < 2; mt++) {
                LDSM_X4(aH[mt][0], aH[mt][1], aH[mt][2], aH[mt][3],
                        aOffH + (mt * 16 * 40 + kk) * 2);
                LDSM_X4(aL[mt][0], aL[mt][1], aL[mt][2], aL[mt][3],
                        aOffL + (mt * 16 * 40 + kk) * 2);
            }
#pragma unroll
            for (int g = 0; g < 4; g++) {
                uint32_t bH[4], bL[4];
                LDSM_X4T(bH[0], bH[1], bH[2], bH[3], bOffH + (kk * 136 + g * 16) * 2);
                LDSM_X4T(bL[0], bL[1], bL[2], bL[3], bOffL + (kk * 136 + g * 16) * 2);
#pragma unroll
                for (int mt = 0; mt < 2; mt++) {
                    MMA16816(acc[mt][g * 2],     aH[mt], bH[0], bH[1]);
                    MMA16816(acc[mt][g * 2],     aL[mt], bH[0], bH[1]);
                    MMA16816(acc[mt][g * 2],     aH[mt], bL[0], bL[1]);
                    MMA16816(acc[mt][g * 2 + 1], aH[mt], bH[2], bH[3]);
                    MMA16816(acc[mt][g * 2 + 1], aL[mt], bH[2], bH[3]);
                    MMA16816(acc[mt][g * 2 + 1], aH[mt], bL[2], bL[3]);
                }
            }
        }
        __syncthreads();
    }

    // epilogue: add bias, store fp32
#pragma unroll
    for (int mt = 0; mt < 2; mt++) {
#pragma unroll
        for (int nf = 0; nf < 8; nf++) {
            int row0 = m0 + wm + mt * 16 + (lane >> 2);
            int col  = n0 + wn + nf * 8 + (lane & 3) * 2;
            float b0 = bias[col], b1 = bias[col + 1];
            float2 v0 = make_float2(acc[mt][nf][0] + b0, acc[mt][nf][1] + b1);
            float2 v1 = make_float2(acc[mt][nf][2] + b0, acc[mt][nf][3] + b1);
            *(float2*)(C + (size_t)row0 * G4 + col)       = v0;
            *(float2*)(C + (size_t)(row0 + 8) * G4 + col) = v1;
        }
    }
}

// ---------------- persistent tensor-core recurrence --------------------------
// 128 CTAs = 32 col-tiles (N=128 gate-cols) x 4 K-splits (K=256), 8 warps.
// Whh chunk resident in smem as bf16 hi/lo [256][136]; h staged per 64-K chunk.
#define WS_STRIDE 136
#define HS_STRIDE 72
#define WS_ELEMS  (256 * WS_STRIDE)
#define HS_ELEMS  (128 * HS_STRIDE)
#define SMEM_PERSIST_BYTES ((2 * WS_ELEMS + 2 * HS_ELEMS) * 2)

__global__ void __launch_bounds__(NTHR) lstm_layer_persist(
    const float* __restrict__ gx,    // [T,BATCH,4096] (bias included)
    const float* __restrict__ Wh,    // [1024,4096] fp32
    float* __restrict__ out,         // [T,BATCH,HDIM]
    float* __restrict__ hN,          // [BATCH,HDIM]
    float* __restrict__ cN) {        // [BATCH,HDIM]
    extern __shared__ __nv_bfloat16 smem[];
    __nv_bfloat16* WsHi = smem;
    __nv_bfloat16* WsLo = WsHi + WS_ELEMS;
    __nv_bfloat16* HsHi = WsLo + WS_ELEMS;
    __nv_bfloat16* HsLo = HsHi + HS_ELEMS;

    const int tid = threadIdx.x, wid = tid >> 5, lane = tid & 31;
    const int bid = blockIdx.x;
    const int ks  = bid & 3;          // K-split
    const int n0  = (bid >> 2) * 128; // gate-col base
    const int k0  = ks * 256;         // K base

    // ---- one-time: Whh chunk -> bf16 hi/lo smem ----
    for (int idx = tid; idx < 256 * 128; idx += NTHR) {
        int k = idx >> 7, n = idx & 127;
        float w = Wh[(size_t)(k0 + k) * G4 + n0 + n];
        __nv_bfloat16 hi = __float2bfloat16_rn(w);
        __nv_bfloat16 lo = __float2bfloat16_rn(w - __bfloat162float(hi));
        WsHi[k * WS_STRIDE + n] = hi;
        WsLo[k * WS_STRIDE + n] = lo;
    }

    // ---- one-time: zero state for owned batch row (row = bid) ----
    {
        const int b = bid;
        for (int i = tid; i < HDIM; i += NTHR) {
            g_h[(size_t)b * HDIM + i] = 0.0f;
            g_c[(size_t)b * HDIM + i] = 0.0f;
            g_h_hi[(size_t)b * HDIM + i] = __float2bfloat16_rn(0.0f);
            g_h_lo[(size_t)b * HDIM + i] = __float2bfloat16_rn(0.0f);
        }
    }
    grid_sync();

    // ldmatrix lane bases
    const uint32_t aBaseH = smem_u32(HsHi) + ((16 * wid + (lane & 15)) * HS_STRIDE + (lane >> 4) * 8) * 2;
    const uint32_t aBaseL = smem_u32(HsLo) + ((16 * wid + (lane & 15)) * HS_STRIDE + (lane >> 4) * 8) * 2;
    const uint32_t bBaseH = smem_u32(WsHi) + (((lane & 15)) * WS_STRIDE + (lane >> 4) * 8) * 2;
    const uint32_t bBaseL = smem_u32(WsLo) + (((lane & 15)) * WS_STRIDE + (lane >> 4) * 8) * 2;

    const int b = bid;
    const int mylen = g_len[b];

    for (int t = 0; t < T_STEPS; t++) {
        float acc[16][4];
#pragma unroll
        for (int f = 0; f < 16; f++)
#pragma unroll
            for (int v = 0; v < 4; v++) acc[f][v] = 0.0f;

        // ===== GEMM: gates_part = h[:, k0:k0+256] @ Whh_chunk =====
#pragma unroll 1
        for (int kc = 0; kc < 4; kc++) {
            // stage h chunk (128 x 64 bf16 hi/lo), L1-bypassing loads
#pragma unroll
            for (int i = 0; i < 4; i++) {
                int idx = tid + i * 256;
                int r = idx >> 3, c8 = idx & 7;
                const uint4* srcH = (const uint4*)(g_h_hi + (size_t)r * HDIM + k0 + kc * 64) + c8;
                const uint4* srcL = (const uint4*)(g_h_lo + (size_t)r * HDIM + k0 + kc * 64) + c8;
                *(uint4*)&HsHi[r * HS_STRIDE + c8 * 8] = __ldcg(srcH);
                *(uint4*)&HsLo[r * HS_STRIDE + c8 * 8] = __ldcg(srcL);
            }
            __syncthreads();

#pragma unroll
            for (int kk = 0; kk < 64; kk += 16) {
                uint32_t aH[4], aL[4];
                LDSM_X4(aH[0], aH[1], aH[2], aH[3], aBaseH + kk * 2);
                LDSM_X4(aL[0], aL[1], aL[2], aL[3], aBaseL + kk * 2);
                const uint32_t bRow = (uint32_t)(kc * 64 + kk) * (WS_STRIDE * 2);
#pragma unroll
                for (int g = 0; g < 8; g++) {
                    uint32_t bH[4], bL[4];
                    LDSM_X4T(bH[0], bH[1], bH[2], bH[3], bBaseH + bRow + g * 32);
                    LDSM_X4T(bL[0], bL[1], bL[2], bL[3], bBaseL + bRow + g * 32);
                    MMA16816(acc[g * 2],     aH, bH[0], bH[1]);
                    MMA16816(acc[g * 2],     aL, bH[0], bH[1]);
                    MMA16816(acc[g * 2],     aH, bL[0], bL[1]);
                    MMA16816(acc[g * 2 + 1], aH, bH[2], bH[3]);
                    MMA16816(acc[g * 2 + 1], aL, bH[2], bH[3]);
                    MMA16816(acc[g * 2 + 1], aH, bL[2], bL[3]);
                }
            }
            __syncthreads();
        }

        // ===== write partials (fp32) =====
        {
            const int row0 = 16 * wid + (lane >> 2);
            float* base0 = g_part + ((size_t)ks * BATCH + row0) * G4 + n0;
            float* base1 = base0 + 8 * G4;
#pragma unroll
            for (int f = 0; f < 16; f++) {
                int col = (f >> 1) * 16 + (f & 1) * 8 + (lane & 3) * 2;
                *(float2*)(base0 + col) = make_float2(acc[f][0], acc[f][1]);
                *(float2*)(base1 + col) = make_float2(acc[f][2], acc[f][3]);
            }
        }
        grid_sync();

        // ===== cell update: CTA b owns batch row b (1024 h-cols) =====
        {
            const float* gxt = gx + ((size_t)t * BATCH + b) * G4;
            const bool msk = (t < mylen);
            float* outp = out + ((size_t)t * BATCH + b) * HDIM;
            const float* p0 = g_part + ((size_t)0 * BATCH + b) * G4;
            const float* p1 = g_part + ((size_t)1 * BATCH + b) * G4;
            const float* p2 = g_part + ((size_t)2 * BATCH + b) * G4;
            const float* p3 = g_part + ((size_t)3 * BATCH + b) * G4;
#pragma unroll
            for (int j = 0; j < 4; j++) {
                int hc = tid + j * 256;
                float I = gxt[hc]        + __ldcg(p0 + hc)        + __ldcg(p1 + hc)
                                         + __ldcg(p2 + hc)        + __ldcg(p3 + hc);
                float F = gxt[1024 + hc] + __ldcg(p0 + 1024 + hc) + __ldcg(p1 + 1024 + hc)
                                         + __ldcg(p2 + 1024 + hc) + __ldcg(p3 + 1024 + hc);
                float O = gxt[2048 + hc] + __ldcg(p0 + 2048 + hc) + __ldcg(p1 + 2048 + hc)
                                         + __ldcg(p2 + 2048 + hc) + __ldcg(p3 + 2048 + hc);
                float G = gxt[3072 + hc] + __ldcg(p0 + 3072 + hc) + __ldcg(p1 + 3072 + hc)
                                         + __ldcg(p2 + 3072 + hc) + __ldcg(p3 + 3072 + hc);
                size_t gi = (size_t)b * HDIM + hc;
                float cp = g_c[gi];
                float c1 = sigf(F + 1.0f) * cp + sigf(I) * tanhf(G);
                float h1 = sigf(O) * tanhf(c1);
                if (msk) {
                    g_c[gi] = c1;
                    g_h[gi] = h1;
                    __nv_bfloat16 hh = __float2bfloat16_rn(h1);
                    g_h_hi[gi] = hh;
                    g_h_lo[gi] = __float2bfloat16_rn(h1 - __bfloat162float(hh));
                    outp[hc] = h1;
                } else {
                    outp[hc] = 0.0f;
                }
            }
        }
        grid_sync();
    }

    // final h/c for this layer
#pragma unroll
    for (int j = 0; j < 4; j++) {
        int hc = tid + j * 256;
        size_t gi = (size_t)b * HDIM + hc;
        hN[gi] = g_h[gi];
        cN[gi] = g_c[gi];
    }
}

// ---------------- launch -----------------------------------------------------
extern "C" void kernel_launch(void* const* d_in, const int* in_sizes, int n_in,
                              void* d_out, int out_size) {
    (void)in_sizes; (void)n_in; (void)out_size;

    const float* x    = (const float*)d_in[0];   // [512,128,1024]
    const int*   lraw = (const int*)d_in[1];     // [128] int32 or int64
    const float* Wih  = (const float*)d_in[2];   // [2,1024,4096]
    const float* Whh  = (const float*)d_in[3];   // [2,1024,4096]
    const float* bias = (const float*)d_in[4];   // [2,4096]

    float* out = (float*)d_out;                         // [512,128,1024]
    float* hN  = out + (size_t)T_STEPS * BATCH * HDIM;  // [2,128,1024]
    float* cN  = hN + 2 * BATCH * HDIM;                 // [2,128,1024]

    float* gx;
    cudaGetSymbolAddress((void**)&gx, g_gx);

    cudaFuncSetAttribute(lstm_layer_persist,
                         cudaFuncAttributeMaxDynamicSharedMemorySize,
                         SMEM_PERSIST_BYTES);

    decode_lengths<<<1, 128>>>(lraw);

    for (int l = 0; l < 2; l++) {
        const float* in = (l == 0) ? x : out;
        const float* Wi = Wih + (size_t)l * HDIM * G4;
        const float* Wh = Whh + (size_t)l * HDIM * G4;
        const float* bi = bias + (size_t)l * G4;

        gemm_gx_mma<<<dim3(32, 512), 256>>>(in, Wi, bi, gx);
        lstm_layer_persist<<<NBLK, NTHR, SMEM_PERSIST_BYTES>>>(
            gx, Wh, out,
            hN + (size_t)l * BATCH * HDIM,
            cN + (size_t)l * BATCH * HDIM);
    }
}

// round 5
// speedup vs baseline: 2.6766x; 1.0611x over previous
#include <cuda_runtime.h>
#include <cuda_bf16.h>
#include <cstdint>

// ---------------- problem constants ----------------
#define T_STEPS 512
#define BATCH   128
#define HDIM    1024
#define G4      4096
#define NBLK    128      // persistent CTAs (<=148 SMs, co-resident)
#define NTHR    512      // threads per persistent CTA (16 warps)

// ---------------- warp MMA helpers (mma.sync -> HMMA) -----------------------
__device__ __forceinline__ uint32_t smem_u32(const void* p) {
    uint32_t a;
    asm("{ .reg .u64 t; cvta.to.shared.u64 t, %1; cvt.u32.u64 %0, t; }"
        : "=r"(a) : "l"(p));
    return a;
}

#define LDSM_X4(r0, r1, r2, r3, addr)                                          \
    asm volatile("ldmatrix.sync.aligned.m8n8.x4.shared.b16 {%0,%1,%2,%3}, [%4];" \
                 : "=r"(r0), "=r"(r1), "=r"(r2), "=r"(r3) : "r"(addr))

#define LDSM_X4T(r0, r1, r2, r3, addr)                                         \
    asm volatile("ldmatrix.sync.aligned.m8n8.x4.trans.shared.b16 {%0,%1,%2,%3}, [%4];" \
                 : "=r"(r0), "=r"(r1), "=r"(r2), "=r"(r3) : "r"(addr))

// D += A(16x16 bf16, row) * B(16x8 bf16, col), fp32 accum
#define MMA16816(d, a, b0, b1)                                                 \
    asm volatile("mma.sync.aligned.m16n8k16.row.col.f32.bf16.bf16.f32 "        \
                 "{%0,%1,%2,%3}, {%4,%5,%6,%7}, {%8,%9}, {%0,%1,%2,%3};"       \
                 : "+f"((d)[0]), "+f"((d)[1]), "+f"((d)[2]), "+f"((d)[3])      \
                 : "r"((a)[0]), "r"((a)[1]), "r"((a)[2]), "r"((a)[3]),         \
                   "r"(b0), "r"(b1))

// ---------------- static device scratch ----------------
__device__ float          g_gx[(size_t)T_STEPS * BATCH * G4];   // 1 GiB
__device__ float          g_h  [BATCH * HDIM];
__device__ float          g_c  [BATCH * HDIM];
__device__ __nv_bfloat16  g_h_hi[BATCH * HDIM];
__device__ __nv_bfloat16  g_h_lo[BATCH * HDIM];
__device__ float          g_part[(size_t)4 * BATCH * G4];       // 4 K-split partials
__device__ int            g_len[BATCH];

__device__ unsigned          g_count = 0;
__device__ volatile unsigned g_gen   = 0;

// ---------------- helpers ----------------
__device__ __forceinline__ float sigf(float x) { return 1.0f / (1.0f + expf(-x)); }

__device__ __forceinline__ void grid_sync() {
    __threadfence();
    __syncthreads();
    if (threadIdx.x == 0) {
        unsigned my = g_gen;
        unsigned old = atomicAdd(&g_count, 1u);
        if (old == NBLK - 1) {
            g_count = 0;
            __threadfence();
            g_gen = my + 1;
        } else {
            while (g_gen == my) { }
        }
    }
    __syncthreads();
}

__global__ void decode_lengths(const int* __restrict__ lraw) {
    __shared__ int odd_nonzero;
    if (threadIdx.x == 0) odd_nonzero = 0;
    __syncthreads();
    if (threadIdx.x < 64) {
        if (lraw[2 * threadIdx.x + 1] != 0) atomicOr(&odd_nonzero, 1);
    }
    __syncthreads();
    int len = odd_nonzero ? lraw[threadIdx.x] : lraw[2 * threadIdx.x];
    g_len[threadIdx.x] = len;
}

// ---------------- big GEMM: gx = A[M,1024] @ W[1024,4096] + bias ------------
// bf16x3 split on tensor cores. CTA tile 128x128, BK=32, 8 warps (32x64 each).
__global__ void __launch_bounds__(256) gemm_gx_mma(
    const float* __restrict__ A, const float* __restrict__ W,
    const float* __restrict__ bias, float* __restrict__ C) {
    __shared__ __nv_bfloat16 AsHi[128][40];
    __shared__ __nv_bfloat16 AsLo[128][40];
    __shared__ __nv_bfloat16 BsHi[32][136];
    __shared__ __nv_bfloat16 BsLo[32][136];

    const int m0 = blockIdx.y * 128, n0 = blockIdx.x * 128;
    const int tid = threadIdx.x, wid = tid >> 5, lane = tid & 31;
    const int wm = (wid & 3) * 32;
    const int wn = (wid >> 2) * 64;

    float acc[2][8][4];
#pragma unroll
    for (int i = 0; i < 2; i++)
#pragma unroll
        for (int j = 0; j < 8; j++)
#pragma unroll
            for (int v = 0; v < 4; v++) acc[i][j][v] = 0.0f;

    const uint32_t aOffH = smem_u32(AsHi) + ((wm + (lane & 15)) * 40 + (lane >> 4) * 8) * 2;
    const uint32_t aOffL = smem_u32(AsLo) + ((wm + (lane & 15)) * 40 + (lane >> 4) * 8) * 2;
    const uint32_t bOffH = smem_u32(BsHi) + ((lane & 15) * 136 + wn + (lane >> 4) * 8) * 2;
    const uint32_t bOffL = smem_u32(BsLo) + ((lane & 15) * 136 + wn + (lane >> 4) * 8) * 2;

    for (int k0 = 0; k0 < 1024; k0 += 32) {
#pragma unroll
        for (int i = 0; i < 4; i++) {
            int idx = tid + i * 256;
            int r = idx >> 3, c = (idx & 7) * 4;
            float4 v = *(const float4*)(A + (size_t)(m0 + r) * 1024 + k0 + c);
            __nv_bfloat16 h0 = __float2bfloat16_rn(v.x);
            __nv_bfloat16 h1 = __float2bfloat16_rn(v.y);
            __nv_bfloat16 h2 = __float2bfloat16_rn(v.z);
            __nv_bfloat16 h3 = __float2bfloat16_rn(v.w);
            __nv_bfloat16 l0 = __float2bfloat16_rn(v.x - __bfloat162float(h0));
            __nv_bfloat16 l1 = __float2bfloat16_rn(v.y - __bfloat162float(h1));
            __nv_bfloat16 l2 = __float2bfloat16_rn(v.z - __bfloat162float(h2));
            __nv_bfloat16 l3 = __float2bfloat16_rn(v.w - __bfloat162float(h3));
            *(__nv_bfloat162*)&AsHi[r][c]     = __halves2bfloat162(h0, h1);
            *(__nv_bfloat162*)&AsHi[r][c + 2] = __halves2bfloat162(h2, h3);
            *(__nv_bfloat162*)&AsLo[r][c]     = __halves2bfloat162(l0, l1);
            *(__nv_bfloat162*)&AsLo[r][c + 2] = __halves2bfloat162(l2, l3);
        }
#pragma unroll
        for (int i = 0; i < 4; i++) {
            int idx = tid + i * 256;
            int kr = idx >> 5, nc = (idx & 31) * 4;
            float4 v = *(const float4*)(W + (size_t)(k0 + kr) * G4 + n0 + nc);
            __nv_bfloat16 h0 = __float2bfloat16_rn(v.x);
            __nv_bfloat16 h1 = __float2bfloat16_rn(v.y);
            __nv_bfloat16 h2 = __float2bfloat16_rn(v.z);
            __nv_bfloat16 h3 = __float2bfloat16_rn(v.w);
            __nv_bfloat16 l0 = __float2bfloat16_rn(v.x - __bfloat162float(h0));
            __nv_bfloat16 l1 = __float2bfloat16_rn(v.y - __bfloat162float(h1));
            __nv_bfloat16 l2 = __float2bfloat16_rn(v.z - __bfloat162float(h2));
            __nv_bfloat16 l3 = __float2bfloat16_rn(v.w - __bfloat162float(h3));
            *(__nv_bfloat162*)&BsHi[kr][nc]     = __halves2bfloat162(h0, h1);
            *(__nv_bfloat162*)&BsHi[kr][nc + 2] = __halves2bfloat162(h2, h3);
            *(__nv_bfloat162*)&BsLo[kr][nc]     = __halves2bfloat162(l0, l1);
            *(__nv_bfloat162*)&BsLo[kr][nc + 2] = __halves2bfloat162(l2, l3);
        }
        __syncthreads();

#pragma unroll
        for (int ks = 0; ks < 2; ks++) {
            const int kk = ks * 16;
            uint32_t aH[2][4], aL[2][4];
#pragma unroll
            for (int mt = 0; mt < 2; mt++) {
                LDSM_X4(aH[mt][0], aH[mt][1], aH[mt][2], aH[mt][3],
                        aOffH + (mt * 16 * 40 + kk) * 2);
                LDSM_X4(aL[mt][0], aL[mt][1], aL[mt][2], aL[mt][3],
                        aOffL + (mt * 16 * 40 + kk) * 2);
            }
#pragma unroll
            for (int g = 0; g < 4; g++) {
                uint32_t bH[4], bL[4];
                LDSM_X4T(bH[0], bH[1], bH[2], bH[3], bOffH + (kk * 136 + g * 16) * 2);
                LDSM_X4T(bL[0], bL[1], bL[2], bL[3], bOffL + (kk * 136 + g * 16) * 2);
#pragma unroll
                for (int mt = 0; mt < 2; mt++) {
                    MMA16816(acc[mt][g * 2],     aH[mt], bH[0], bH[1]);
                    MMA16816(acc[mt][g * 2],     aL[mt], bH[0], bH[1]);
                    MMA16816(acc[mt][g * 2],     aH[mt], bL[0], bL[1]);
                    MMA16816(acc[mt][g * 2 + 1], aH[mt], bH[2], bH[3]);
                    MMA16816(acc[mt][g * 2 + 1], aL[mt], bH[2], bH[3]);
                    MMA16816(acc[mt][g * 2 + 1], aH[mt], bL[2], bL[3]);
                }
            }
        }
        __syncthreads();
    }

#pragma unroll
    for (int mt = 0; mt < 2; mt++) {
#pragma unroll
        for (int nf = 0; nf < 8; nf++) {
            int row0 = m0 + wm + mt * 16 + (lane >> 2);
            int col  = n0 + wn + nf * 8 + (lane & 3) * 2;
            float b0 = bias[col], b1 = bias[col + 1];
            float2 v0 = make_float2(acc[mt][nf][0] + b0, acc[mt][nf][1] + b1);
            float2 v1 = make_float2(acc[mt][nf][2] + b0, acc[mt][nf][3] + b1);
            *(float2*)(C + (size_t)row0 * G4 + col)       = v0;
            *(float2*)(C + (size_t)(row0 + 8) * G4 + col) = v1;
        }
    }
}

// ---------------- persistent tensor-core recurrence --------------------------
// 128 CTAs = 32 col-tiles (N=128 gate-cols) x 4 K-splits (K=256), 16 warps.
// Whh chunk resident in smem bf16 hi/lo [256][136]; h staged per 64-K chunk
// with double buffering (prefetch to regs overlapped with MMA).
#define WS_STRIDE 136
#define HS_STRIDE 72
#define WS_ELEMS  (256 * WS_STRIDE)
#define HS_BUF    (128 * HS_STRIDE)                   // one 64-K chunk
#define SMEM_PERSIST_BYTES ((2 * WS_ELEMS + 4 * HS_BUF) * 2)

__global__ void __launch_bounds__(NTHR) lstm_layer_persist(
    const float* __restrict__ gx,    // [T,BATCH,4096] (bias included)
    const float* __restrict__ Wh,    // [1024,4096] fp32
    float* __restrict__ out,         // [T,BATCH,HDIM]
    float* __restrict__ hN,          // [BATCH,HDIM]
    float* __restrict__ cN) {        // [BATCH,HDIM]
    extern __shared__ __nv_bfloat16 smem[];
    __nv_bfloat16* WsHi = smem;
    __nv_bfloat16* WsLo = WsHi + WS_ELEMS;
    __nv_bfloat16* HsHi = WsLo + WS_ELEMS;            // 2 buffers
    __nv_bfloat16* HsLo = HsHi + 2 * HS_BUF;          // 2 buffers

    const int tid = threadIdx.x, wid = tid >> 5, lane = tid & 31;
    const int bid = blockIdx.x;
    const int ks  = bid & 3;          // K-split
    const int n0  = (bid >> 2) * 128; // gate-col base
    const int k0  = ks * 256;         // K base
    const int wm  = (wid & 3) * 32;   // warp row base (2 m16)
    const int wn  = (wid >> 2) * 32;  // warp col base (4 n8)

    // ---- one-time: Whh chunk -> bf16 hi/lo smem ----
    for (int idx = tid; idx < 256 * 128; idx += NTHR) {
        int k = idx >> 7, n = idx & 127;
        float w = Wh[(size_t)(k0 + k) * G4 + n0 + n];
        __nv_bfloat16 hi = __float2bfloat16_rn(w);
        __nv_bfloat16 lo = __float2bfloat16_rn(w - __bfloat162float(hi));
        WsHi[k * WS_STRIDE + n] = hi;
        WsLo[k * WS_STRIDE + n] = lo;
    }

    // ---- one-time: zero state for owned batch row (row = bid) ----
    {
        const int b = bid;
        for (int i = tid; i < HDIM; i += NTHR) {
            g_h[(size_t)b * HDIM + i] = 0.0f;
            g_c[(size_t)b * HDIM + i] = 0.0f;
            g_h_hi[(size_t)b * HDIM + i] = __float2bfloat16_rn(0.0f);
            g_h_lo[(size_t)b * HDIM + i] = __float2bfloat16_rn(0.0f);
        }
    }
    grid_sync();

    // staging indices: 512 threads, 128 rows x 8 uint4 per row (hi), same lo
    const int sr = tid >> 2;          // 0..127
    const int sq = tid & 3;           // handles uint4 sq and sq+4

    // ldmatrix lane bases
    const uint32_t hsB = smem_u32(HsHi);
    const uint32_t hlB = smem_u32(HsLo);
    const uint32_t aRow = ((uint32_t)(wm + (lane & 15)) * HS_STRIDE + (lane >> 4) * 8) * 2;
    const uint32_t bByteH = smem_u32(WsHi) + (((lane & 15)) * WS_STRIDE + wn + (lane >> 4) * 8) * 2;
    const uint32_t bByteL = smem_u32(WsLo) + (((lane & 15)) * WS_STRIDE + wn + (lane >> 4) * 8) * 2;

    const int b = bid;
    const int mylen = g_len[b];

    for (int t = 0; t < T_STEPS; t++) {
        float acc[2][4][4];
#pragma unroll
        for (int mt = 0; mt < 2; mt++)
#pragma unroll
            for (int nf = 0; nf < 4; nf++)
#pragma unroll
                for (int v = 0; v < 4; v++) acc[mt][nf][v] = 0.0f;

        // ---- preload chunk 0 ----
        {
            const uint4* sH = (const uint4*)(g_h_hi + (size_t)sr * HDIM + k0);
            const uint4* sL = (const uint4*)(g_h_lo + (size_t)sr * HDIM + k0);
            uint4 vh0 = __ldcg(sH + sq), vh1 = __ldcg(sH + sq + 4);
            uint4 vl0 = __ldcg(sL + sq), vl1 = __ldcg(sL + sq + 4);
            uint4* dH = (uint4*)&HsHi[sr * HS_STRIDE];
            uint4* dL = (uint4*)&HsLo[sr * HS_STRIDE];
            dH[sq] = vh0; dH[sq + 4] = vh1;
            dL[sq] = vl0; dL[sq + 4] = vl1;
        }
        __syncthreads();

#pragma unroll
        for (int kc = 0; kc < 4; kc++) {
            const int buf = kc & 1;
            // prefetch next chunk into registers (latency hidden by MMAs)
            uint4 vh0, vh1, vl0, vl1;
            if (kc < 3) {
                const uint4* sH = (const uint4*)(g_h_hi + (size_t)sr * HDIM + k0 + (kc + 1) * 64);
                const uint4* sL = (const uint4*)(g_h_lo + (size_t)sr * HDIM + k0 + (kc + 1) * 64);
                vh0 = __ldcg(sH + sq); vh1 = __ldcg(sH + sq + 4);
                vl0 = __ldcg(sL + sq); vl1 = __ldcg(sL + sq + 4);
            }

            const uint32_t hOff = hsB + (uint32_t)buf * (HS_BUF * 2) + aRow;
            const uint32_t lOff = hlB + (uint32_t)buf * (HS_BUF * 2) + aRow;
#pragma unroll
            for (int kk = 0; kk < 64; kk += 16) {
                uint32_t aH[2][4], aL[2][4];
#pragma unroll
                for (int mt = 0; mt < 2; mt++) {
                    LDSM_X4(aH[mt][0], aH[mt][1], aH[mt][2], aH[mt][3],
                            hOff + (mt * 16 * HS_STRIDE + kk) * 2);
                    LDSM_X4(aL[mt][0], aL[mt][1], aL[mt][2], aL[mt][3],
                            lOff + (mt * 16 * HS_STRIDE + kk) * 2);
                }
                const uint32_t bRow = (uint32_t)(kc * 64 + kk) * (WS_STRIDE * 2);
#pragma unroll
                for (int g = 0; g < 2; g++) {
                    uint32_t bH[4], bL[4];
                    LDSM_X4T(bH[0], bH[1], bH[2], bH[3], bByteH + bRow + g * 32);
                    LDSM_X4T(bL[0], bL[1], bL[2], bL[3], bByteL + bRow + g * 32);
#pragma unroll
                    for (int mt = 0; mt < 2; mt++) {
                        MMA16816(acc[mt][g * 2],     aH[mt], bH[0], bH[1]);
                        MMA16816(acc[mt][g * 2],     aL[mt], bH[0], bH[1]);
                        MMA16816(acc[mt][g * 2],     aH[mt], bL[0], bL[1]);
                        MMA16816(acc[mt][g * 2 + 1], aH[mt], bH[2], bH[3]);
                        MMA16816(acc[mt][g * 2 + 1], aL[mt], bH[2], bH[3]);
                        MMA16816(acc[mt][g * 2 + 1], aH[mt], bL[2], bL[3]);
                    }
                }
            }

            if (kc < 3) {
                const int nb = buf ^ 1;
                uint4* dH = (uint4*)&HsHi[nb * HS_BUF + sr * HS_STRIDE];
                uint4* dL = (uint4*)&HsLo[nb * HS_BUF + sr * HS_STRIDE];
                dH[sq] = vh0; dH[sq + 4] = vh1;
                dL[sq] = vl0; dL[sq + 4] = vl1;
            }
            __syncthreads();
        }

        // ===== write partials (fp32) =====
        {
            const int prow = wm + (lane >> 2);
            float* pb = g_part + ((size_t)ks * BATCH + prow) * G4 + n0 + wn;
#pragma unroll
            for (int mt = 0; mt < 2; mt++) {
#pragma unroll
                for (int nf = 0; nf < 4; nf++) {
                    int coloff = (nf >> 1) * 16 + (nf & 1) * 8 + (lane & 3) * 2;
                    *(float2*)(pb + (size_t)(mt * 16) * G4 + coloff) =
                        make_float2(acc[mt][nf][0], acc[mt][nf][1]);
                    *(float2*)(pb + (size_t)(mt * 16 + 8) * G4 + coloff) =
                        make_float2(acc[mt][nf][2], acc[mt][nf][3]);
                }
            }
        }
        grid_sync();

        // ===== cell update: CTA b owns batch row b (1024 h-cols) =====
        {
            const float* gxt = gx + ((size_t)t * BATCH + b) * G4;
            const bool msk = (t < mylen);
            float* outp = out + ((size_t)t * BATCH + b) * HDIM;
            const float* p0 = g_part + ((size_t)0 * BATCH + b) * G4;
            const float* p1 = g_part + ((size_t)1 * BATCH + b) * G4;
            const float* p2 = g_part + ((size_t)2 * BATCH + b) * G4;
            const float* p3 = g_part + ((size_t)3 * BATCH + b) * G4;
#pragma unroll
            for (int j = 0; j < 2; j++) {
                int hc = tid + j * 512;
                float I = gxt[hc]        + __ldcg(p0 + hc)        + __ldcg(p1 + hc)
                                         + __ldcg(p2 + hc)        + __ldcg(p3 + hc);
                float F = gxt[1024 + hc] + __ldcg(p0 + 1024 + hc) + __ldcg(p1 + 1024 + hc)
                                         + __ldcg(p2 + 1024 + hc) + __ldcg(p3 + 1024 + hc);
                float O = gxt[2048 + hc] + __ldcg(p0 + 2048 + hc) + __ldcg(p1 + 2048 + hc)
                                         + __ldcg(p2 + 2048 + hc) + __ldcg(p3 + 2048 + hc);
                float G = gxt[3072 + hc] + __ldcg(p0 + 3072 + hc) + __ldcg(p1 + 3072 + hc)
                                         + __ldcg(p2 + 3072 + hc) + __ldcg(p3 + 3072 + hc);
                size_t gi = (size_t)b * HDIM + hc;
                float cp = g_c[gi];
                float c1 = sigf(F + 1.0f) * cp + sigf(I) * tanhf(G);
                float h1 = sigf(O) * tanhf(c1);
                if (msk) {
                    g_c[gi] = c1;
                    g_h[gi] = h1;
                    __nv_bfloat16 hh = __float2bfloat16_rn(h1);
                    g_h_hi[gi] = hh;
                    g_h_lo[gi] = __float2bfloat16_rn(h1 - __bfloat162float(hh));
                    outp[hc] = h1;
                } else {
                    outp[hc] = 0.0f;
                }
            }
        }
        grid_sync();
    }

    // final h/c for this layer
#pragma unroll
    for (int j = 0; j < 2; j++) {
        int hc = tid + j * 512;
        size_t gi = (size_t)b * HDIM + hc;
        hN[gi] = g_h[gi];
        cN[gi] = g_c[gi];
    }
}

// ---------------- launch -----------------------------------------------------
extern "C" void kernel_launch(void* const* d_in, const int* in_sizes, int n_in,
                              void* d_out, int out_size) {
    (void)in_sizes; (void)n_in; (void)out_size;

    const float* x    = (const float*)d_in[0];   // [512,128,1024]
    const int*   lraw = (const int*)d_in[1];     // [128] int32 or int64
    const float* Wih  = (const float*)d_in[2];   // [2,1024,4096]
    const float* Whh  = (const float*)d_in[3];   // [2,1024,4096]
    const float* bias = (const float*)d_in[4];   // [2,4096]

    float* out = (float*)d_out;                         // [512,128,1024]
    float* hN  = out + (size_t)T_STEPS * BATCH * HDIM;  // [2,128,1024]
    float* cN  = hN + 2 * BATCH * HDIM;                 // [2,128,1024]

    float* gx;
    cudaGetSymbolAddress((void**)&gx, g_gx);

    cudaFuncSetAttribute(lstm_layer_persist,
                         cudaFuncAttributeMaxDynamicSharedMemorySize,
                         SMEM_PERSIST_BYTES);

    decode_lengths<<<1, 128>>>(lraw);

    for (int l = 0; l < 2; l++) {
        const float* in = (l == 0) ? x : out;
        const float* Wi = Wih + (size_t)l * HDIM * G4;
        const float* Wh = Whh + (size_t)l * HDIM * G4;
        const float* bi = bias + (size_t)l * G4;

        gemm_gx_mma<<<dim3(32, 512), 256>>>(in, Wi, bi, gx);
        lstm_layer_persist<<<NBLK, NTHR, SMEM_PERSIST_BYTES>>>(
            gx, Wh, out,
            hN + (size_t)l * BATCH * HDIM,
            cN + (size_t)l * BATCH * HDIM);
    }
}